// round 17
// baseline (speedup 1.0000x reference)
#include <cuda_runtime.h>

#define N_Q    4
#define COLS   512
#define RPW    4          // rows per warp
#define BLOCK  256

// ---------------------------------------------------------------------------
__device__ __forceinline__ float fast_atan(float x)
{
    float a   = fabsf(x);
    bool  inv = a > 1.0f;
    float z   = inv ? __fdividef(1.0f, a) : a;
    float z2  = z * z;
    float p   = -0.0117212f;
    p = fmaf(p, z2,  0.05265332f);
    p = fmaf(p, z2, -0.11643287f);
    p = fmaf(p, z2,  0.19354346f);
    p = fmaf(p, z2, -0.33262347f);
    p = fmaf(p, z2,  0.99997726f);
    p = p * z;
    float r = inv ? (1.57079632679489662f - p) : p;
    return copysignf(r, x);
}

#define SHX8(v) __shfl_xor_sync(0xFFu, (v), 1)

// ---------------------------------------------------------------------------
// Fused: GEMV (all 32 lanes) -> repack -> 2-lane-per-row circuit (lanes 0-7)
// ---------------------------------------------------------------------------
__global__ void __launch_bounds__(BLOCK) qnet_kernel(
    const float* __restrict__ x,       // [B, 512]
    const float* __restrict__ pre_w,   // [4, 512]
    const float* __restrict__ pre_b,   // [4]
    const float* __restrict__ u3p,     // [4, 3]
    const float* __restrict__ post_w,  // [2, 4]
    const float* __restrict__ post_b,  // [2]
    float* __restrict__ out,           // [B, 2]
    int B)
{
    __shared__ float4 wsh[N_Q * (COLS / 4)];   // 8 KB
    __shared__ float  gsh[N_Q][7];             // per-block U3 gate constants

    const int tid = threadIdx.x;

    // per-block U3 gate precompute (no cross-block dependency)
    if (tid < N_Q) {
        float th = u3p[tid * 3 + 0];
        float ph = u3p[tid * 3 + 1];
        float la = u3p[tid * 3 + 2];
        float st, ct; sincosf(0.5f * th, &st, &ct);
        float sl, cl; sincosf(la, &sl, &cl);
        float sf, cf; sincosf(ph, &sf, &cf);
        gsh[tid][0] = ct;
        gsh[tid][1] = -cl * st;                 // m01r
        gsh[tid][2] = -sl * st;                 // m01i
        gsh[tid][3] =  cf * st;                 // m10r
        gsh[tid][4] =  sf * st;                 // m10i
        gsh[tid][5] = (cf * cl - sf * sl) * ct; // m11r
        gsh[tid][6] = (sf * cl + cf * sl) * ct; // m11i
    }

    #pragma unroll
    for (int i = tid; i < N_Q * (COLS / 4); i += BLOCK)
        wsh[i] = reinterpret_cast<const float4*>(pre_w)[i];
    __syncthreads();

    const int warp = (blockIdx.x * BLOCK + tid) >> 5;
    const int lane = tid & 31;
    const int row0 = warp * RPW;
    if (row0 >= B) return;

    const float4* __restrict__ x4 = reinterpret_cast<const float4*>(x);

    // ---------------- GEMV: 4 rows per warp ----------------
    float acc[RPW][N_Q];
    #pragma unroll
    for (int r = 0; r < RPW; r++)
        #pragma unroll
        for (int j = 0; j < N_Q; j++) acc[r][j] = 0.f;

    #pragma unroll
    for (int k = 0; k < 4; k++) {
        const int c4 = lane + 32 * k;
        float4 xv[RPW];
        #pragma unroll
        for (int r = 0; r < RPW; r++) {
            int gr = row0 + r;
            xv[r] = x4[(size_t)(gr < B ? gr : B - 1) * 128 + c4];
        }
        float4 w0 = wsh[0 * 128 + c4];
        float4 w1 = wsh[1 * 128 + c4];
        float4 w2 = wsh[2 * 128 + c4];
        float4 w3 = wsh[3 * 128 + c4];
        #pragma unroll
        for (int r = 0; r < RPW; r++) {
            acc[r][0] += xv[r].x * w0.x + xv[r].y * w0.y + xv[r].z * w0.z + xv[r].w * w0.w;
            acc[r][1] += xv[r].x * w1.x + xv[r].y * w1.y + xv[r].z * w1.z + xv[r].w * w1.w;
            acc[r][2] += xv[r].x * w2.x + xv[r].y * w2.y + xv[r].z * w2.z + xv[r].w * w2.w;
            acc[r][3] += xv[r].x * w3.x + xv[r].y * w3.y + xv[r].z * w3.z + xv[r].w * w3.w;
        }
    }

    // butterfly reduce; lane (r*4+j) keeps sum for row0+r, feature j
    float val = 0.f;
    #pragma unroll
    for (int r = 0; r < RPW; r++)
        #pragma unroll
        for (int j = 0; j < N_Q; j++) {
            float v = acc[r][j];
            v += __shfl_xor_sync(0xFFFFFFFFu, v, 16);
            v += __shfl_xor_sync(0xFFFFFFFFu, v, 8);
            v += __shfl_xor_sync(0xFFFFFFFFu, v, 4);
            v += __shfl_xor_sync(0xFFFFFFFFu, v, 2);
            v += __shfl_xor_sync(0xFFFFFFFFu, v, 1);
            if (lane == r * N_Q + j) val = v;
        }

    // repack: circuit lane c (0-7) gets features of row (c>>1) from lanes (c>>1)*4+k
    float fin[N_Q];
    #pragma unroll
    for (int k = 0; k < N_Q; k++)
        fin[k] = __shfl_sync(0xFFFFFFFFu, val, ((lane >> 1) & 3) * N_Q + k);

    if (lane >= 8) return;   // lanes 8-31 done; circuit uses mask 0xFF below

    const int row = row0 + (lane >> 1);
    const int p   = lane & 1;

    // ---------------- angles ----------------
    float ry[N_Q], rz[N_Q];
    #pragma unroll
    for (int k = 0; k < N_Q; k++) {
        float pp = (fin[k] + __ldg(&pre_b[k])) * 0.1f;
        float t;
        asm("tanh.approx.f32 %0, %1;" : "=f"(t) : "f"(pp));
        float qin = t * 1.57079632679489662f;
        ry[k] = fast_atan(qin);
        rz[k] = fast_atan(qin * qin);
    }

    // ---- H|0000> = uniform 0.25 real, then RY (state stays real) ----
    float r[8];
    #pragma unroll
    for (int i = 0; i < 8; i++) r[i] = 0.25f;

    // RY qubit 0 (cross-lane)
    {
        float s, c;
        __sincosf(0.5f * ry[0], &s, &c);
        float se = p ? s : -s;
        #pragma unroll
        for (int i = 0; i < 8; i++) {
            float rp = SHX8(r[i]);
            r[i] = fmaf(se, rp, c * r[i]);
        }
    }
    // RY qubits 1..3 (local)
    #pragma unroll
    for (int q = 1; q < N_Q; q++) {
        float s, c;
        __sincosf(0.5f * ry[q], &s, &c);
        const int m = 4 >> (q - 1);
        #pragma unroll
        for (int i = 0; i < 8; i++) {
            if (!(i & m)) {
                float a = r[i], b = r[i | m];
                r[i]     = c * a - s * b;
                r[i | m] = s * a + c * b;
            }
        }
    }

    // ---- RZ (diagonal, lane-local), seeded with qubit-0 sign ----
    float pr[8], pi[8];
    {
        float ss0, cc0;
        __sincosf(0.5f * rz[0], &ss0, &cc0);
        pr[0] = cc0;
        pi[0] = p ? ss0 : -ss0;
    }
    #pragma unroll
    for (int q = 1; q < N_Q; q++) {
        float ss, cc;
        __sincosf(0.5f * rz[q], &ss, &cc);
        const int n = 1 << (q - 1);
        #pragma unroll
        for (int t = n - 1; t >= 0; t--) {
            float a = pr[t], b = pi[t];
            pr[2 * t + 1] = a * cc - b * ss;
            pi[2 * t + 1] = a * ss + b * cc;
            pr[2 * t]     = a * cc + b * ss;
            pi[2 * t]     = b * cc - a * ss;
        }
    }
    float re[8], im[8];
    #pragma unroll
    for (int i = 0; i < 8; i++) {
        re[i] = r[i] * pr[i];
        im[i] = r[i] * pi[i];
    }

    // ---- composed 8-CNOT permutation: P = [0,6,12,10,11,13,7,1,15,9,3,5,4,2,8,14]
    {
        float xr2 = SHX8(re[2]), xi2 = SHX8(im[2]);
        float xr3 = SHX8(re[3]), xi3 = SHX8(im[3]);
        float xr4 = SHX8(re[4]), xi4 = SHX8(im[4]);
        float xr5 = SHX8(re[5]), xi5 = SHX8(im[5]);
        float o0r = re[0], o0i = im[0], o1r = re[1], o1i = im[1];
        float o6r = re[6], o6i = im[6], o7r = re[7], o7i = im[7];
        if (p == 0) {
            re[0] = o0r; im[0] = o0i;
            re[1] = o6r; im[1] = o6i;
            re[2] = xr4; im[2] = xi4;
            re[3] = xr2; im[3] = xi2;
            re[4] = xr3; im[4] = xi3;
            re[5] = xr5; im[5] = xi5;
            re[6] = o7r; im[6] = o7i;
            re[7] = o1r; im[7] = o1i;
        } else {
            re[0] = o7r; im[0] = o7i;
            re[1] = o1r; im[1] = o1i;
            re[2] = xr3; im[2] = xi3;
            re[3] = xr5; im[3] = xi5;
            re[4] = xr4; im[4] = xi4;
            re[5] = xr2; im[5] = xi2;
            re[6] = o0r; im[6] = o0i;
            re[7] = o6r; im[7] = o6i;
        }
    }

    // ---- U3 qubit 0 (cross-lane) ----
    {
        float ct   = gsh[0][0];
        float m01r = gsh[0][1], m01i = gsh[0][2];
        float m10r = gsh[0][3], m10i = gsh[0][4];
        float m11r = gsh[0][5], m11i = gsh[0][6];
        float ar = p ? m11r : ct;
        float ai = p ? m11i : 0.f;
        float br = p ? m10r : m01r;
        float bi = p ? m10i : m01i;
        #pragma unroll
        for (int i = 0; i < 8; i++) {
            float wr = SHX8(re[i]);
            float wi = SHX8(im[i]);
            float vr = re[i], vi = im[i];
            re[i] = ar * vr - ai * vi + br * wr - bi * wi;
            im[i] = ar * vi + ai * vr + br * wi + bi * wr;
        }
    }
    // ---- U3 qubits 1..3 (local) ----
    #pragma unroll
    for (int q = 1; q < N_Q; q++) {
        float ct   = gsh[q][0];
        float m01r = gsh[q][1], m01i = gsh[q][2];
        float m10r = gsh[q][3], m10i = gsh[q][4];
        float m11r = gsh[q][5], m11i = gsh[q][6];
        const int m = 4 >> (q - 1);
        #pragma unroll
        for (int i = 0; i < 8; i++) {
            if (!(i & m)) {
                int j = i | m;
                float a_r = re[i], a_i = im[i];
                float b_r = re[j], b_i = im[j];
                re[i] = ct * a_r + m01r * b_r - m01i * b_i;
                im[i] = ct * a_i + m01r * b_i + m01i * b_r;
                re[j] = m10r * a_r - m10i * a_i + m11r * b_r - m11i * b_i;
                im[j] = m10i * a_r + m10r * a_i + m11i * b_r + m11r * b_i;
            }
        }
    }

    // ---- Z expectations + head ----
    float e[N_Q] = {0.f, 0.f, 0.f, 0.f};
    #pragma unroll
    for (int i = 0; i < 8; i++) {
        float pp = re[i] * re[i] + im[i] * im[i];
        e[0] += pp;
        e[1] += (i & 4) ? -pp : pp;
        e[2] += (i & 2) ? -pp : pp;
        e[3] += (i & 1) ? -pp : pp;
    }
    e[0] = p ? -e[0] : e[0];
    #pragma unroll
    for (int q = 0; q < N_Q; q++)
        e[q] += SHX8(e[q]);

    if (row >= B) return;
    float o = __ldg(&post_b[p]);
    #pragma unroll
    for (int k = 0; k < N_Q; k++)
        o += e[k] * __ldg(&post_w[p * N_Q + k]);
    out[2 * (size_t)row + p] = o;
}

extern "C" void kernel_launch(void* const* d_in, const int* in_sizes, int n_in,
                              void* d_out, int out_size)
{
    const float* x      = (const float*)d_in[0];
    const float* pre_w  = (const float*)d_in[1];
    const float* pre_b  = (const float*)d_in[2];
    const float* u3p    = (const float*)d_in[3];
    const float* post_w = (const float*)d_in[4];
    const float* post_b = (const float*)d_in[5];
    float* out = (float*)d_out;

    int B = in_sizes[0] / COLS;
    int warps = (B + RPW - 1) / RPW;
    int grid  = (warps * 32 + BLOCK - 1) / BLOCK;
    qnet_kernel<<<grid, BLOCK>>>(x, pre_w, pre_b, u3p, post_w, post_b, out, B);
}